// round 16
// baseline (speedup 1.0000x reference)
#include <cuda_runtime.h>

#define BATCH 4
#define SEQL  4096
#define DIN   128
#define NST   16
#define TCH   32
#define NCH   128   /* 32-l chunks */
#define NSC   256   /* 16-l sub-chunks per batch */
#define SP34  34    /* su/ys/r pitch ([d][t], even -> u64 aligned) */

typedef unsigned long long u64;

#define FMA2(d, a, b, c) asm("fma.rn.f32x2 %0, %1, %2, %3;" : "=l"(d) : "l"(a), "l"(b), "l"(c))
#define MUL2(d, a, b)    asm("mul.rn.f32x2 %0, %1, %2;" : "=l"(d) : "l"(a), "l"(b))
#define UNPK2(x, y, in)  asm("mov.b64 {%0, %1}, %2;" : "=f"(x), "=f"(y) : "l"(in))
#define PK1(d, x)        asm("mov.b64 %0, {%1, %1};" : "=l"(d) : "f"(x))
#define PKP(d, x, y)     asm("mov.b64 %0, {%1, %2};" : "=l"(d) : "f"(x), "f"(y))

#define CPA16(dst, src)  asm volatile("cp.async.cg.shared.global [%0], [%1], 16;" :: "r"(dst), "l"(src) : "memory")
#define CPCOM()          asm volatile("cp.async.commit_group;" ::: "memory")
#define CPWAIT1()        asm volatile("cp.async.wait_group 1;" ::: "memory")
#define CPWAIT0()        asm volatile("cp.async.wait_group 0;" ::: "memory")

// ---------------- scratch (device globals; no allocation) ----------------
__device__ float g_xr  [BATCH*SEQL*256];   // in_proj output (u | res), row-major [l][256]
__device__ float g_hp  [BATCH*NSC*DIN*32]; // per-sub-chunk [h_end(16)|P(16)] -> H_init
__device__ float g_xmid[BATCH*64*SEQL];    // between mambas, k-major [b][c][l]
__device__ float g_w1t [2][64*256];        // in_proj W transposed [k][n]
__device__ float g_wxt [2][128*64];        // x_proj W transposed, zero-padded to 64
__device__ float g_wot [2][128*64];        // out_proj W transposed
__device__ float g_Ab  [2][DIN*NST];       // A = -exp(Alog)
__device__ int   g_Afl [2];                // 1 if A[d][n] == (n+1)*A[d][0]
__device__ unsigned g_ctr = 0;             // grid-barrier ticket counter (monotonic)

__device__ __forceinline__ float softplusf(float x) {
    return x > 15.f ? x : __logf(1.f + __expf(x));
}
__device__ __forceinline__ float siluf(float x) {
    return x / (1.f + __expf(-x));
}

// ---------------- prep: both mambas in one launch ----------------
__global__ void prep_k(const float* __restrict__ iw0, const float* __restrict__ xp0,
                       const float* __restrict__ ow0, const float* __restrict__ al0,
                       const float* __restrict__ iw1, const float* __restrict__ xp1,
                       const float* __restrict__ ow1, const float* __restrict__ al1,
                       float* __restrict__ w1t, float* __restrict__ wxt,
                       float* __restrict__ wot, float* __restrict__ Ab) {
    int m = blockIdx.y;
    const float* in_w  = m ? iw1 : iw0;
    const float* xproj = m ? xp1 : xp0;
    const float* out_w = m ? ow1 : ow0;
    const float* Alog  = m ? al1 : al0;
    float* w1 = w1t + m*16384;
    float* wx = wxt + m*8192;
    float* wo = wot + m*8192;
    float* Am = Ab  + m*2048;
    int idx = blockIdx.x * 256 + threadIdx.x;
    if (idx < 16384) { int k = idx >> 8, n = idx & 255; w1[idx] = in_w[n*64 + k]; return; }
    idx -= 16384;
    if (idx < 8192)  { int k = idx >> 6, n = idx & 63; wx[idx] = (n < 36) ? xproj[n*128 + k] : 0.f; return; }
    idx -= 8192;
    if (idx < 8192)  { int k = idx >> 6, n = idx & 63; wo[idx] = out_w[n*128 + k]; return; }
    idx -= 8192;
    if (idx < 2048)  Am[idx] = -expf(Alog[idx]);
}

__global__ void chkA_k(const float* __restrict__ A0, const float* __restrict__ A1,
                       int* __restrict__ fl) {
    const float* A = blockIdx.x ? A1 : A0;
    __shared__ int ok;
    if (threadIdx.x == 0) ok = 1;
    __syncthreads();
    int bad = 0;
    for (int e = threadIdx.x; e < DIN*NST; e += 256) {
        int d = e >> 4, n = e & 15;
        float expv = (float)(n + 1) * A[d*16];
        if (fabsf(A[e] - expv) > 1e-5f * fabsf(expv) + 1e-20f) bad = 1;
    }
    if (bad) atomicAnd(&ok, 0);
    __syncthreads();
    if (threadIdx.x == 0) fl[blockIdx.x] = ok;
}

// ---------------- pipelined GEMM (in_proj only): X k-major; tile 64L x 64N ----------------
__global__ __launch_bounds__(256) void gemm_k(
    const float* __restrict__ X, const float* __restrict__ Wt, float* __restrict__ Out,
    int K, int Nld, int Nout)
{
    extern __shared__ float sm[];
    int tid = threadIdx.x;
    int l0 = blockIdx.x << 6;
    int n0 = blockIdx.y << 6;
    int b  = blockIdx.z;
    const float* Xb = X + (long)b * K * SEQL;
    int lj = tid >> 4, ng = tid & 15;
    int lb = lj << 2;
    unsigned smb = (unsigned)__cvta_generic_to_shared(sm);
    int ntiles = K >> 5;

    {
#pragma unroll
        for (int i = 0; i < 2; i++) {
            int e = tid + (i << 8);
            int k = e >> 4, lq = e & 15;
            CPA16(smb + (((k << 6) + (lq << 2)) << 2),
                  Xb + (long)k * SEQL + l0 + (lq << 2));
        }
#pragma unroll
        for (int i = 0; i < 2; i++) {
            int e = tid + (i << 8);
            int k = e >> 4, nq = e & 15;
            CPA16(smb + 16384u + (((k << 6) + (nq << 2)) << 2),
                  Wt + (long)k * Nld + n0 + (nq << 2));
        }
        CPCOM();
    }

    u64 acc[2][4];
#pragma unroll
    for (int p = 0; p < 2; p++)
#pragma unroll
        for (int c = 0; c < 4; c++) acc[p][c] = 0ULL;

    for (int tt = 0; tt < ntiles; tt++) {
        int s = tt & 1;
        if (tt + 1 < ntiles) {
            int kofs = (tt + 1) << 5;
            int s2 = s ^ 1;
#pragma unroll
            for (int i = 0; i < 2; i++) {
                int e = tid + (i << 8);
                int k = e >> 4, lq = e & 15;
                CPA16(smb + (((s2 << 11) + (k << 6) + (lq << 2)) << 2),
                      Xb + (long)(kofs + k) * SEQL + l0 + (lq << 2));
            }
#pragma unroll
            for (int i = 0; i < 2; i++) {
                int e = tid + (i << 8);
                int k = e >> 4, nq = e & 15;
                CPA16(smb + 16384u + (((s2 << 11) + (k << 6) + (nq << 2)) << 2),
                      Wt + (long)(kofs + k) * Nld + n0 + (nq << 2));
            }
            CPCOM();
            CPWAIT1();
        } else {
            CPWAIT0();
        }
        __syncthreads();
        const float* xs = sm + (s << 11);
        const float* ws = sm + 4096 + (s << 11);
#pragma unroll 8
        for (int kk = 0; kk < 32; kk++) {
            ulonglong2 av = *(const ulonglong2*)&xs[(kk << 6) + lb];
            float4 wv = *(const float4*)&ws[(kk << 6) + (ng << 2)];
            u64 b0, b1, b2, b3;
            PK1(b0, wv.x); PK1(b1, wv.y); PK1(b2, wv.z); PK1(b3, wv.w);
            FMA2(acc[0][0], av.x, b0, acc[0][0]); FMA2(acc[0][1], av.x, b1, acc[0][1]);
            FMA2(acc[0][2], av.x, b2, acc[0][2]); FMA2(acc[0][3], av.x, b3, acc[0][3]);
            FMA2(acc[1][0], av.y, b0, acc[1][0]); FMA2(acc[1][1], av.y, b1, acc[1][1]);
            FMA2(acc[1][2], av.y, b2, acc[1][2]); FMA2(acc[1][3], av.y, b3, acc[1][3]);
        }
        __syncthreads();
    }

#pragma unroll
    for (int p = 0; p < 2; p++) {
        float lo[4], hi[4];
#pragma unroll
        for (int c = 0; c < 4; c++) UNPK2(lo[c], hi[c], acc[p][c]);
        long r0 = ((long)b*SEQL + l0 + lb + 2*p) * Nout + n0 + (ng << 2);
        *(float4*)&Out[r0]        = make_float4(lo[0], lo[1], lo[2], lo[3]);
        *(float4*)&Out[r0 + Nout] = make_float4(hi[0], hi[1], hi[2], hi[3]);
    }
}

// ---------------- grid barrier (all 512 blocks resident by construction) ----------------
__device__ __forceinline__ void gridbar(int tid) {
    __syncthreads();
    if (tid == 0) {
        __threadfence();
        unsigned t = atomicAdd(&g_ctr, 1u);
        unsigned target = (t & ~511u) + 512u;
        volatile unsigned* p = &g_ctr;
        while ((int)(*p - target) < 0) __nanosleep(64);
    }
    __syncthreads();
    __threadfence();
}

// ---------------- MEGA v2: 256 threads; conv + x_proj + scan + out_proj + LN ----------------
// grid (NCH, BATCH) = 512 blocks x 256 thr; smem 57344B -> 4 blocks/SM, all resident.
// smem floats: su[128][34] | ys[128][34] | xds[32][36] | U[4480]
//   U = union of: halo (35*128=4480), W k-tile (32*64), r/dt store [128][34], LN staging [32][65]
__global__ __launch_bounds__(256, 4) void mega_k(
    const float* __restrict__ xr,
    const float* __restrict__ cw,  const float* __restrict__ cb,
    const float* __restrict__ wxt,
    const float* __restrict__ Ap,
    const float* __restrict__ dtw, const float* __restrict__ dtb,
    const float* __restrict__ Dp,
    const float* __restrict__ wot,
    const float* __restrict__ lng, const float* __restrict__ lnb,
    float* __restrict__ hp,
    float* __restrict__ gout,
    const int* __restrict__ flagp)
{
    extern __shared__ float sm[];
    float* su  = sm;            // [128 d][34 t]
    float* ys  = sm + 4352;     // [128 d][34 t]  (du, then gated y)
    float* xds = sm + 8704;     // [32 t][36]
    float* U   = sm + 9856;     // union (4480 floats)

    int tid = threadIdx.x;
    int c = blockIdx.x, b = blockIdx.y;
    int lcl = c*TCH;
    long lc = (long)b*SEQL + lcl;

    // ===== Phase A: conv + silu -> su [d][t] =====
    for (int e = tid; e < 35*32; e += 256) {
        int row = e >> 5, d4 = e & 31;
        int lg = lcl - 3 + row;
        float4 v = (lg >= 0) ? *(const float4*)&xr[((long)b*SEQL + lg)*256 + (d4 << 2)]
                             : make_float4(0.f, 0.f, 0.f, 0.f);
        *(float4*)&U[row*128 + (d4 << 2)] = v;
    }
    __syncthreads();
    {
        int dd = tid & 127, half = tid >> 7;
        float4 wv = *(const float4*)&cw[dd*4];
        float bias = __ldg(&cb[dd]);
        int l0h = half << 4;
#pragma unroll 8
        for (int j = 0; j < 16; j++) {
            int l = l0h + j;
            float s = fmaf(wv.x, U[l*128 + dd], fmaf(wv.y, U[(l+1)*128 + dd],
                      fmaf(wv.z, U[(l+2)*128 + dd], fmaf(wv.w, U[(l+3)*128 + dd], bias))));
            su[dd*SP34 + l] = siluf(s);
        }
    }
    __syncthreads();

    // ===== Phase B: x_proj GEMM (32l x 36n x K=128), A=su[k][l] =====
    int ng = tid & 15, lj = tid >> 4;   // lj 0..15 -> l pair (2lj, 2lj+1)
    {
        u64 acc[4] = {0ULL, 0ULL, 0ULL, 0ULL};
        for (int kt = 0; kt < 4; kt++) {
            for (int e = tid; e < 512; e += 256) {
                int k = e >> 4, nq = e & 15;
                *(float4*)&U[(k << 6) + (nq << 2)] =
                    *(const float4*)&wxt[(kt*32 + k)*64 + (nq << 2)];
            }
            __syncthreads();
#pragma unroll 8
            for (int kk = 0; kk < 32; kk++) {
                u64 a = *(const u64*)&su[(kt*32 + kk)*SP34 + (lj << 1)];
                float4 wv = *(const float4*)&U[(kk << 6) + (ng << 2)];
                u64 b0, b1, b2, b3;
                PK1(b0, wv.x); PK1(b1, wv.y); PK1(b2, wv.z); PK1(b3, wv.w);
                FMA2(acc[0], a, b0, acc[0]); FMA2(acc[1], a, b1, acc[1]);
                FMA2(acc[2], a, b2, acc[2]); FMA2(acc[3], a, b3, acc[3]);
            }
            __syncthreads();
        }
        if (ng < 9) {
#pragma unroll
            for (int cc = 0; cc < 4; cc++) {
                int n = (ng << 2) + cc;
                float lo, hi;
                UNPK2(lo, hi, acc[cc]);
                xds[(lj << 1)*36 + n]       = lo;
                xds[((lj << 1) + 1)*36 + n] = hi;
            }
        }
    }
    __syncthreads();

    // ===== Precompute (per half-chunk): du -> ys, r|dt -> U; S over own 16 t =====
    int d = tid >> 1, sub = tid & 1;
    int t0 = sub << 4;
    float4 w = *(const float4*)&dtw[d*4];
    float bias = __ldg(&dtb[d]);
    float Dd = __ldg(&Dp[d]);
    int structured = *flagp;
    float A0 = Ap[d*NST];
    float* o = hp + (((long)(b*NSC + (c << 1) + sub))*DIN + d)*32;
    float S = 0.f;
#pragma unroll 8
    for (int j = 0; j < 16; j++) {
        int t = t0 + j;
        const float* xt = xds + t*36;
        float dt = fmaf(xt[0], w.x, fmaf(xt[1], w.y, fmaf(xt[2], w.z, fmaf(xt[3], w.w, bias))));
        dt = softplusf(dt);
        S += dt;
        ys[d*SP34 + t] = dt * su[d*SP34 + t];
        U[d*SP34 + t] = structured ? __expf(dt * A0) : dt;
    }

    // ===== pass 1: scan own 16-t sub-chunk from h=0 =====
    if (structured) {
        u64 h2[8];
#pragma unroll
        for (int p = 0; p < 8; p++) h2[p] = 0ULL;
#pragma unroll 4
        for (int j = 0; j < 16; j++) {
            int t = t0 + j;
            const float* xt = xds + t*36;
            float r = U[d*SP34 + t];
            float r2 = r*r, r4 = r2*r2, r8 = r4*r4;
            u64 du2, q0, v2, v4, v8, q1, q2, q3, q4, q5, q6, q7;
            PK1(du2, ys[d*SP34 + t]);
            PKP(q0, r, r2);
            PK1(v2, r2); PK1(v4, r4); PK1(v8, r8);
            MUL2(q1, q0, v2); MUL2(q2, q0, v4); MUL2(q3, q1, v4);
            MUL2(q4, q0, v8); MUL2(q5, q1, v8); MUL2(q6, q2, v8); MUL2(q7, q3, v8);
            u64 qs[8] = {q0, q1, q2, q3, q4, q5, q6, q7};
#pragma unroll
            for (int p = 0; p < 8; p++) {
                u64 bp = *(const u64*)&xt[4 + 2*p];
                u64 m;
                MUL2(m, du2, bp);
                FMA2(h2[p], qs[p], h2[p], m);
            }
        }
#pragma unroll
        for (int p = 0; p < 8; p++) *(u64*)&o[2*p] = h2[p];
        float q = __expf(S * A0), qc = q;
#pragma unroll
        for (int n = 0; n < NST; n++) { o[16 + n] = qc; qc *= q; }
    } else {
        float Ar[NST], h[NST];
#pragma unroll
        for (int n = 0; n < NST; n++) { Ar[n] = Ap[d*NST + n]; h[n] = 0.f; }
        for (int j = 0; j < 16; j++) {
            int t = t0 + j;
            const float* xt = xds + t*36;
            float dt = U[d*SP34 + t];
            float du = ys[d*SP34 + t];
#pragma unroll
            for (int n = 0; n < NST; n++) {
                float a = __expf(dt * Ar[n]);
                h[n] = fmaf(a, h[n], du * xt[4 + n]);
            }
        }
#pragma unroll
        for (int n = 0; n < NST; n++) { o[n] = h[n]; o[16 + n] = __expf(S * Ar[n]); }
    }

    gridbar(tid);

    // ===== segmented combine: 131072 threads, 16 segs x 16 sub-chunks per state =====
    {
        int g = (((b*NCH + c) << 8) | tid);   // 0..131071
        int s = g >> 4, seg = g & 15;
        int b2 = s >> 11;
        int dn = s & 2047;
        int off = ((dn >> 4) << 5) + (dn & 15);
        long base = (long)b2 * NSC * (DIN*32) + off + (long)seg * 16 * (DIN*32);
        float he[16], pp[16];
        float H = 0.f, P = 1.f;
#pragma unroll
        for (int j = 0; j < 16; j++) {
            he[j] = hp[base + (long)j*(DIN*32)];
            pp[j] = hp[base + (long)j*(DIN*32) + 16];
        }
#pragma unroll
        for (int j = 0; j < 16; j++) {
            H = fmaf(pp[j], H, he[j]);
            P *= pp[j];
        }
#pragma unroll
        for (int k = 1; k < 16; k <<= 1) {
            float Hu = __shfl_up_sync(0xffffffffu, H, k, 16);
            float Pu = __shfl_up_sync(0xffffffffu, P, k, 16);
            if (seg >= k) { H = fmaf(P, Hu, H); P *= Pu; }
        }
        float Hx = __shfl_up_sync(0xffffffffu, H, 1, 16);
        if (seg == 0) Hx = 0.f;
        float Hc = Hx;
#pragma unroll
        for (int j = 0; j < 16; j++) {
            hp[base + (long)j*(DIN*32)] = Hc;
            Hc = fmaf(pp[j], Hc, he[j]);
        }
    }

    gridbar(tid);

    // ===== pass 3: replay own sub-chunk from H_init; gated output -> ys [d][t] =====
    if (structured) {
        u64 h2[8];
#pragma unroll
        for (int p = 0; p < 8; p++) h2[p] = *(const u64*)&o[2*p];
#pragma unroll 4
        for (int j = 0; j < 16; j++) {
            int t = t0 + j;
            const float* xt = xds + t*36;
            float r = U[d*SP34 + t];
            float du = ys[d*SP34 + t];
            float ut = su[d*SP34 + t];
            float r2 = r*r, r4 = r2*r2, r8 = r4*r4;
            u64 du2, q0, v2, v4, v8, q1, q2, q3, q4, q5, q6, q7, y2 = 0ULL;
            PK1(du2, du);
            PKP(q0, r, r2);
            PK1(v2, r2); PK1(v4, r4); PK1(v8, r8);
            MUL2(q1, q0, v2); MUL2(q2, q0, v4); MUL2(q3, q1, v4);
            MUL2(q4, q0, v8); MUL2(q5, q1, v8); MUL2(q6, q2, v8); MUL2(q7, q3, v8);
            u64 qs[8] = {q0, q1, q2, q3, q4, q5, q6, q7};
#pragma unroll
            for (int p = 0; p < 8; p++) {
                u64 bp = *(const u64*)&xt[4 + 2*p];
                u64 cp = *(const u64*)&xt[20 + 2*p];
                u64 m;
                MUL2(m, du2, bp);
                FMA2(h2[p], qs[p], h2[p], m);
                FMA2(y2, h2[p], cp, y2);
            }
            float ylo, yhi;
            UNPK2(ylo, yhi, y2);
            float rt = xr[(lc + t)*256 + 128 + d];
            ys[d*SP34 + t] = fmaf(ut, Dd, ylo + yhi) * siluf(rt);
        }
    } else {
        float Ar[NST], h[NST];
#pragma unroll
        for (int n = 0; n < NST; n++) { Ar[n] = Ap[d*NST + n]; h[n] = o[n]; }
        for (int j = 0; j < 16; j++) {
            int t = t0 + j;
            const float* xt = xds + t*36;
            float dt = U[d*SP34 + t];
            float du = ys[d*SP34 + t];
            float ut = su[d*SP34 + t];
            float y = 0.f;
#pragma unroll
            for (int n = 0; n < NST; n++) {
                float a = __expf(dt * Ar[n]);
                h[n] = fmaf(a, h[n], du * xt[4 + n]);
                y = fmaf(h[n], xt[20 + n], y);
            }
            float rt = xr[(lc + t)*256 + 128 + d];
            ys[d*SP34 + t] = fmaf(ut, Dd, y) * siluf(rt);
        }
    }
    __syncthreads();

    // ===== Phase E: out_proj GEMM (32l x 64n x K=128) from ys + LayerNorm =====
    {
        u64 acc[4] = {0ULL, 0ULL, 0ULL, 0ULL};
        for (int kt = 0; kt < 4; kt++) {
            for (int e = tid; e < 512; e += 256) {
                int k = e >> 4, nq = e & 15;
                *(float4*)&U[(k << 6) + (nq << 2)] =
                    *(const float4*)&wot[(kt*32 + k)*64 + (nq << 2)];
            }
            __syncthreads();
#pragma unroll 8
            for (int kk = 0; kk < 32; kk++) {
                u64 a = *(const u64*)&ys[(kt*32 + kk)*SP34 + (lj << 1)];
                float4 wv = *(const float4*)&U[(kk << 6) + (ng << 2)];
                u64 b0, b1, b2, b3;
                PK1(b0, wv.x); PK1(b1, wv.y); PK1(b2, wv.z); PK1(b3, wv.w);
                FMA2(acc[0], a, b0, acc[0]); FMA2(acc[1], a, b1, acc[1]);
                FMA2(acc[2], a, b2, acc[2]); FMA2(acc[3], a, b3, acc[3]);
            }
            __syncthreads();
        }
        // stage into st = U [32 l][65]
        float* st = U;
#pragma unroll
        for (int cc = 0; cc < 4; cc++) {
            int n = (ng << 2) + cc;
            float lo, hi;
            UNPK2(lo, hi, acc[cc]);
            st[(lj << 1)*65 + n]       = lo;
            st[((lj << 1) + 1)*65 + n] = hi;
        }
        __syncthreads();
        // LayerNorm: 8 threads per row (32 rows), 8 cols each
        int row = tid >> 3, q8 = tid & 7;
        float v[8], s = 0.f, s2 = 0.f;
#pragma unroll
        for (int j = 0; j < 8; j++) {
            float x = st[row*65 + q8*8 + j];
            v[j] = x; s += x; s2 += x * x;
        }
        s  += __shfl_xor_sync(0xffffffffu, s, 1, 8);
        s2 += __shfl_xor_sync(0xffffffffu, s2, 1, 8);
        s  += __shfl_xor_sync(0xffffffffu, s, 2, 8);
        s2 += __shfl_xor_sync(0xffffffffu, s2, 2, 8);
        s  += __shfl_xor_sync(0xffffffffu, s, 4, 8);
        s2 += __shfl_xor_sync(0xffffffffu, s2, 4, 8);
        float mean = s * 0.015625f;
        float var  = s2 * 0.015625f - mean * mean;
        float rstd = rsqrtf(var + 1e-5f);
#pragma unroll
        for (int j = 0; j < 8; j++) {
            int n = q8*8 + j;
            st[row*65 + n] = (v[j] - mean) * rstd * __ldg(&lng[n]) + __ldg(&lnb[n]);
        }
        __syncthreads();
        // transposed coalesced write: gout[b][n][lcl + l]
        for (int e = tid; e < 512; e += 256) {
            int n = e >> 3, l4 = e & 7;
            int l = l4 << 2;
            float4 o4 = make_float4(st[l*65 + n],       st[(l+1)*65 + n],
                                    st[(l+2)*65 + n],   st[(l+3)*65 + n]);
            *(float4*)&gout[((long)b*64 + n)*SEQL + lcl + l] = o4;
        }
    }
}

// ---------------- host ----------------
extern "C" void kernel_launch(void* const* d_in, const int* in_sizes, int n_in,
                              void* d_out, int out_size) {
    const float* x1 = (const float*)d_in[0];
    float* out = (float*)d_out;

    float *xr, *hp, *xmid, *w1t, *wxt, *wot, *Ab;
    int* Afl;
    cudaGetSymbolAddress((void**)&xr,   g_xr);
    cudaGetSymbolAddress((void**)&hp,   g_hp);
    cudaGetSymbolAddress((void**)&xmid, g_xmid);
    cudaGetSymbolAddress((void**)&w1t,  g_w1t);
    cudaGetSymbolAddress((void**)&wxt,  g_wxt);
    cudaGetSymbolAddress((void**)&wot,  g_wot);
    cudaGetSymbolAddress((void**)&Ab,   g_Ab);
    cudaGetSymbolAddress((void**)&Afl,  g_Afl);

    prep_k<<<dim3(136, 2), 256>>>(
        (const float*)d_in[1], (const float*)d_in[4], (const float*)d_in[9], (const float*)d_in[7],
        (const float*)d_in[10], (const float*)d_in[13], (const float*)d_in[18], (const float*)d_in[16],
        w1t, wxt, wot, Ab);
    chkA_k<<<2, 256>>>(Ab, Ab + 2048, Afl);

    const int GSM = 33280;
    const int MSM = (4352 + 4352 + 1152 + 4480) * 4;   // 57344 B -> 4 blocks/SM
    cudaFuncSetAttribute(mega_k, cudaFuncAttributeMaxDynamicSharedMemorySize, MSM);

    for (int m = 0; m < 2; m++) {
        const float* cw  = (const float*)d_in[1 + 9*m + 1];
        const float* cb  = (const float*)d_in[1 + 9*m + 2];
        const float* dtw = (const float*)d_in[1 + 9*m + 4];
        const float* dtb = (const float*)d_in[1 + 9*m + 5];
        const float* Dp  = (const float*)d_in[1 + 9*m + 7];
        const float* lng = (const float*)d_in[19 + 2*m];
        const float* lnb = (const float*)d_in[20 + 2*m];
        const float* Abm = Ab + m*2048;
        const int*   flm = Afl + m;

        const float* Xin = (m == 0) ? x1 : xmid;      // k-major [b][64][4096]
        float* gout = (m == 0) ? xmid : out;          // k-major [b][64][4096]

        // in_proj: K=64, N=256 -> xr row-major [l][256]
        gemm_k<<<dim3(SEQL/64, 4, BATCH), 256, GSM>>>(
            Xin, w1t + m*16384, xr, 64, 256, 256);
        // MEGA v2: conv + x_proj + scan + out_proj + LN, 256 threads
        mega_k<<<dim3(NCH, BATCH), 256, MSM>>>(
            xr, cw, cb, wxt + m*8192, Abm, dtw, dtb, Dp,
            wot + m*8192, lng, lnb, hp, gout, flm);
    }
}